// round 8
// baseline (speedup 1.0000x reference)
#include <cuda_runtime.h>
#include <math.h>
#include <stdint.h>

#define T_STEPS 1024
#define HID     256
#define NSPK    1251
#define F_IN    40

// ---------------- device scratch ----------------
// Self-flagging h exchange: each element is {h, epoch}. epoch == t+1 marks
// h[layer][t][unit] valid. Single 8B atomic store/load = flag + data in one trip.
__device__ float2 g_hx[3][T_STEPS][HID];   // 6 MB

// ---------------- helpers ----------------
__device__ __forceinline__ float poll_h(const float2* p, int epoch) {
    float h; int e;
    do {
        asm volatile("ld.relaxed.gpu.global.v2.b32 {%0,%1}, [%2];"
                     : "=f"(h), "=r"(e) : "l"(p));
    } while (e != epoch);
    return h;
}
__device__ __forceinline__ void pub_h(float2* p, float h, int epoch) {
    asm volatile("st.relaxed.gpu.global.v2.b32 [%0], {%1,%2};"
                 :: "l"(p), "f"(h), "r"(epoch));
}
__device__ __forceinline__ void ffma2(unsigned long long& acc,
                                      unsigned long long a, unsigned long long b) {
    asm("fma.rn.f32x2 %0, %1, %2, %0;" : "+l"(acc) : "l"(a), "l"(b));
}
__device__ __forceinline__ unsigned long long pack2(float a, float b) {
    unsigned long long v;
    asm("mov.b64 %0, {%1,%2};" : "=l"(v) : "f"(a), "f"(b));
    return v;
}
__device__ __forceinline__ float sigf(float x) { return 1.0f / (1.0f + __expf(-x)); }
__device__ __forceinline__ float tanh_fast(float x) {
    return 2.0f / (1.0f + __expf(-2.0f * x)) - 1.0f;
}

// ---------------- init: zero the exchange buffer (epochs must start != t+1) ----------------
__global__ void init_epochs_kernel() {
    int i = blockIdx.x * blockDim.x + threadIdx.x;   // 1536*512 = 786432 = 3*1024*256
    ((float2*)g_hx)[i] = make_float2(0.0f, 0.0f);
}

// ---------------- pipelined 3-layer LSTM ----------------
// grid = 48 CTAs x 512 threads. CTA (l = bid>>4, c = bid&15) owns hidden units
// [16c,16c+16) -> 64 gate rows; W_hh + W_ih slices in registers (f32x2 pairs).
// Exchange protocol per step:
//   tid <  256 : poll own-layer h[t-1][tid]      (epoch t)
//   tid >= 256 : poll upstream  h_{l-1}[t][tid-256] (epoch t+1)   [l>0]
//                stage x[63,t]                                     [l==0]
//   lanes 0-15 of warp0: gates + publish h[t] slice (self-flagged STG.64)
extern "C" __global__ void __launch_bounds__(512, 1)
lstm_pipeline_kernel(
    const float* __restrict__ x,
    const float* __restrict__ wih0, const float* __restrict__ whh0,
    const float* __restrict__ bih0, const float* __restrict__ bhh0,
    const float* __restrict__ wih1, const float* __restrict__ whh1,
    const float* __restrict__ bih1, const float* __restrict__ bhh1,
    const float* __restrict__ wih2, const float* __restrict__ whh2,
    const float* __restrict__ bih2, const float* __restrict__ bhh2)
{
    __shared__ float h_s[HID];           // own layer h(t-1)
    __shared__ float hp_s[HID];          // upstream layer h(t)  (l>0)
    __shared__ float x_s[F_IN];          // x[63,t,:]            (l==0)
    __shared__ float gbuf[64];           // per-gate-row sums

    const int tid = threadIdx.x;
    const int l   = blockIdx.x >> 4;
    const int c   = blockIdx.x & 15;

    const int r    = tid >> 3;           // 0..63 : gate row within CTA
    const int kc   = tid & 7;            // 0..7  : k-chunk lane
    const int gate = r >> 4, ul = r & 15;
    const int grow = gate * 256 + c * 16 + ul;       // global gate row

    const float* whh = (l == 0) ? whh0 : (l == 1) ? whh1 : whh2;
    const float* wih = (l == 0) ? wih0 : (l == 1) ? wih1 : wih2;
    const float* bih = (l == 0) ? bih0 : (l == 1) ? bih1 : bih2;
    const float* bhh = (l == 0) ? bhh0 : (l == 1) ? bhh1 : bhh2;

    // W_hh slice: quad q covers floats [32q+4kc, 32q+4kc+4) -> conflict-free LDS.128
    unsigned long long wh[16];
    #pragma unroll
    for (int q = 0; q < 8; q++) {
        const float* pr = whh + grow * HID + 32 * q + 4 * kc;
        wh[2*q]   = *(const unsigned long long*)(pr);
        wh[2*q+1] = *(const unsigned long long*)(pr + 2);
    }
    unsigned long long wi[16];
    float wx[5];
    if (l == 0) {
        #pragma unroll
        for (int j = 0; j < 5; j++) wx[j] = wih[grow * F_IN + kc * 5 + j];
    } else {
        #pragma unroll
        for (int q = 0; q < 8; q++) {
            const float* pr = wih + grow * HID + 32 * q + 4 * kc;
            wi[2*q]   = *(const unsigned long long*)(pr);
            wi[2*q+1] = *(const unsigned long long*)(pr + 2);
        }
    }
    const float brow = bih[grow] + bhh[grow];        // used by kc==0 lane

    // zero h(-1)
    if (tid < 64) *(float4*)&h_s[tid * 4] = make_float4(0.f, 0.f, 0.f, 0.f);

    float xr = 0.0f;
    if (l == 0 && tid >= 256 && tid < 256 + F_IN)
        xr = x[(63 * T_STEPS + 0) * F_IN + (tid - 256)];

    float cst = 0.0f;                    // cell state (lanes 0-15 of warp0)
    __syncthreads();

    for (int t = 0; t < T_STEPS; t++) {
        // ---- single-trip self-flagging exchange ----
        if (tid < 256) {
            if (t > 0) h_s[tid] = poll_h(&g_hx[l][t-1][tid], t);
        } else if (l > 0) {
            hp_s[tid - 256] = poll_h(&g_hx[l-1][t][tid - 256], t + 1);
        } else {
            const int j = tid - 256;
            if (j < F_IN) {
                x_s[j] = xr;
                if (t + 1 < T_STEPS)
                    xr = x[(63 * T_STEPS + (t + 1)) * F_IN + j];
            }
        }
        __syncthreads();

        // ---- matvec: 32-wide k-slice, packed f32x2 FMAs ----
        unsigned long long acc = 0ULL;
        {
            const float* hb = &h_s[4 * kc];
            #pragma unroll
            for (int q = 0; q < 8; q++) {
                float4 hv = *(const float4*)(hb + 32 * q);
                ffma2(acc, wh[2*q],   pack2(hv.x, hv.y));
                ffma2(acc, wh[2*q+1], pack2(hv.z, hv.w));
            }
        }
        float px = 0.0f;
        if (l > 0) {
            const float* pb = &hp_s[4 * kc];
            #pragma unroll
            for (int q = 0; q < 8; q++) {
                float4 hv = *(const float4*)(pb + 32 * q);
                ffma2(acc, wi[2*q],   pack2(hv.x, hv.y));
                ffma2(acc, wi[2*q+1], pack2(hv.z, hv.w));
            }
        } else {
            #pragma unroll
            for (int j = 0; j < 5; j++) px = fmaf(wx[j], x_s[kc * 5 + j], px);
        }
        float lo, hi;
        asm("mov.b64 {%0,%1}, %2;" : "=f"(lo), "=f"(hi) : "l"(acc));
        float p = lo + hi + px;

        p += __shfl_xor_sync(0xffffffffu, p, 1);
        p += __shfl_xor_sync(0xffffffffu, p, 2);
        p += __shfl_xor_sync(0xffffffffu, p, 4);
        if (kc == 0) gbuf[r] = p + brow;
        __syncthreads();

        // ---- gates + self-flagged publish (warp0 lanes 0-15) ----
        if (tid < 16) {
            float gi = gbuf[tid],      gf = gbuf[16 + tid];
            float gc = gbuf[32 + tid], go = gbuf[48 + tid];
            float ii = sigf(gi), ff = sigf(gf);
            float cc = tanh_fast(gc), oo = sigf(go);
            cst = ff * cst + ii * cc;
            float hn = oo * tanh_fast(cst);
            pub_h(&g_hx[l][t][c * 16 + tid], hn, t + 1);
        }
    }
}

// ---------------- classifier: logits = h2 @ W_lin^T + b, log_softmax ----------------
__global__ __launch_bounds__(512, 1) void classifier_kernel(
    const float* __restrict__ wlin,
    const float* __restrict__ blin,
    float* __restrict__ out)
{
    __shared__ float lg[4 * NSPK];
    __shared__ float hsm[4 * HID];
    __shared__ float rbuf[16];

    const int b    = blockIdx.x;
    const int t0   = b * 4;
    const int tid  = threadIdx.x;
    const int lane = tid & 31;
    const int wd   = tid >> 5;

    for (int i = tid; i < 4 * HID; i += 512)
        hsm[i] = g_hx[2][t0 + (i >> 8)][i & 255].x;
    __syncthreads();

    float hr[4][8];
    #pragma unroll
    for (int t = 0; t < 4; t++)
        #pragma unroll
        for (int j = 0; j < 8; j++) hr[t][j] = hsm[t * HID + lane * 8 + j];

    for (int o = wd; o < NSPK; o += 16) {
        const float4* wp = (const float4*)(wlin + o * HID + lane * 8);
        float4 w0 = wp[0], w1 = wp[1];
        float wv[8] = {w0.x, w0.y, w0.z, w0.w, w1.x, w1.y, w1.z, w1.w};
        float a0 = 0.f, a1 = 0.f, a2 = 0.f, a3 = 0.f;
        #pragma unroll
        for (int j = 0; j < 8; j++) {
            float wj = wv[j];
            a0 = fmaf(wj, hr[0][j], a0);
            a1 = fmaf(wj, hr[1][j], a1);
            a2 = fmaf(wj, hr[2][j], a2);
            a3 = fmaf(wj, hr[3][j], a3);
        }
        #pragma unroll
        for (int off = 16; off > 0; off >>= 1) {
            a0 += __shfl_xor_sync(0xffffffffu, a0, off);
            a1 += __shfl_xor_sync(0xffffffffu, a1, off);
            a2 += __shfl_xor_sync(0xffffffffu, a2, off);
            a3 += __shfl_xor_sync(0xffffffffu, a3, off);
        }
        if (lane == 0) {
            float bb = blin[o];
            lg[0 * NSPK + o] = a0 + bb;
            lg[1 * NSPK + o] = a1 + bb;
            lg[2 * NSPK + o] = a2 + bb;
            lg[3 * NSPK + o] = a3 + bb;
        }
    }
    __syncthreads();

    for (int t = 0; t < 4; t++) {
        float m = -1e30f;
        for (int o = tid; o < NSPK; o += 512) m = fmaxf(m, lg[t * NSPK + o]);
        #pragma unroll
        for (int off = 16; off > 0; off >>= 1)
            m = fmaxf(m, __shfl_xor_sync(0xffffffffu, m, off));
        if (lane == 0) rbuf[wd] = m;
        __syncthreads();
        float mm = rbuf[0];
        #pragma unroll
        for (int i = 1; i < 16; i++) mm = fmaxf(mm, rbuf[i]);
        __syncthreads();

        float s = 0.0f;
        for (int o = tid; o < NSPK; o += 512) s += __expf(lg[t * NSPK + o] - mm);
        #pragma unroll
        for (int off = 16; off > 0; off >>= 1)
            s += __shfl_xor_sync(0xffffffffu, s, off);
        if (lane == 0) rbuf[wd] = s;
        __syncthreads();
        float ss = 0.0f;
        #pragma unroll
        for (int i = 0; i < 16; i++) ss += rbuf[i];
        float lse = mm + logf(ss);

        for (int o = tid; o < NSPK; o += 512)
            out[(size_t)(t0 + t) * NSPK + o] = lg[t * NSPK + o] - lse;
        __syncthreads();
    }
}

// ---------------- launch ----------------
extern "C" void kernel_launch(void* const* d_in, const int* in_sizes, int n_in,
                              void* d_out, int out_size)
{
    const float* x    = (const float*)d_in[0];
    const float* wih0 = (const float*)d_in[1];
    const float* whh0 = (const float*)d_in[2];
    const float* bih0 = (const float*)d_in[3];
    const float* bhh0 = (const float*)d_in[4];
    const float* wih1 = (const float*)d_in[5];
    const float* whh1 = (const float*)d_in[6];
    const float* bih1 = (const float*)d_in[7];
    const float* bhh1 = (const float*)d_in[8];
    const float* wih2 = (const float*)d_in[9];
    const float* whh2 = (const float*)d_in[10];
    const float* bih2 = (const float*)d_in[11];
    const float* bhh2 = (const float*)d_in[12];
    const float* wlin = (const float*)d_in[13];
    const float* blin = (const float*)d_in[14];
    float* out = (float*)d_out;

    init_epochs_kernel<<<1536, 512>>>();
    lstm_pipeline_kernel<<<48, 512>>>(x,
        wih0, whh0, bih0, bhh0,
        wih1, whh1, bih1, bhh1,
        wih2, whh2, bih2, bhh2);
    classifier_kernel<<<256, 512>>>(wlin, blin, out);
}

// round 9
// speedup vs baseline: 1.4213x; 1.4213x over previous
#include <cuda_runtime.h>
#include <math.h>
#include <stdint.h>

#define T_STEPS 1024
#define HID     256
#define NSPK    1251
#define F_IN    40

// ---------------- device scratch ----------------
// Self-flagging h exchange: {h, epoch}; epoch == t+1 marks h[l][t][unit] valid.
// Zero-initialized at module load; reinit kernel re-zeroes at END of each call.
__device__ float2 g_hx[3][T_STEPS][HID];   // 6 MB

// ---------------- helpers ----------------
__device__ __forceinline__ float poll_h(const float2* p, int epoch) {
    float h; int e;
    do {
        asm volatile("ld.relaxed.gpu.global.v2.b32 {%0,%1}, [%2];"
                     : "=f"(h), "=r"(e) : "l"(p));
    } while (e != epoch);
    return h;
}
__device__ __forceinline__ void pub_h(float2* p, float h, int epoch) {
    asm volatile("st.relaxed.gpu.global.v2.b32 [%0], {%1,%2};"
                 :: "l"(p), "f"(h), "r"(epoch));
}
__device__ __forceinline__ void ffma2(unsigned long long& acc,
                                      unsigned long long a, unsigned long long b) {
    asm("fma.rn.f32x2 %0, %1, %2, %0;" : "+l"(acc) : "l"(a), "l"(b));
}
__device__ __forceinline__ unsigned long long pack2(float a, float b) {
    unsigned long long v;
    asm("mov.b64 %0, {%1,%2};" : "=l"(v) : "f"(a), "f"(b));
    return v;
}
__device__ __forceinline__ float sigf(float x) { return 1.0f / (1.0f + __expf(-x)); }
__device__ __forceinline__ float tanh_fast(float x) {
    return 2.0f / (1.0f + __expf(-2.0f * x)) - 1.0f;
}

// ---------------- reinit: zero exchange buffer for the NEXT call ----------------
__global__ void reinit_epochs_kernel() {
    int i = blockIdx.x * blockDim.x + threadIdx.x;   // 1536*512 = 786432
    ((float2*)g_hx)[i] = make_float2(0.0f, 0.0f);
}

// ---------------- pipelined 3-layer LSTM: warp-per-unit, 1 bar/step ----------------
// grid = 48 CTAs x 512 threads. CTA (l = bid>>4, c = bid&15) owns 16 hidden
// units. Warp u handles unit c*16+u: lane = gate*8+kc covers the unit's 4 gate
// rows x 8 k-chunks (32 k each). After the kc shuffle-reduce, all 4 gate sums
// sit in lanes {0,8,16,24}; lane 0 computes the nonlinearities and publishes.
// h_s/hp_s/x_s are parity double-buffered -> single __syncthreads per step.
extern "C" __global__ void __launch_bounds__(512, 1)
lstm_pipeline_kernel(
    const float* __restrict__ x,
    const float* __restrict__ wih0, const float* __restrict__ whh0,
    const float* __restrict__ bih0, const float* __restrict__ bhh0,
    const float* __restrict__ wih1, const float* __restrict__ whh1,
    const float* __restrict__ bih1, const float* __restrict__ bhh1,
    const float* __restrict__ wih2, const float* __restrict__ whh2,
    const float* __restrict__ bih2, const float* __restrict__ bhh2)
{
    __shared__ float h_s [2][HID];       // own layer h(t-1), parity-buffered
    __shared__ float hp_s[2][HID];       // upstream h(t)     (l>0)
    __shared__ float x_s [2][F_IN];      // x[63,t,:]         (l==0)

    const int tid  = threadIdx.x;
    const int l    = blockIdx.x >> 4;
    const int c    = blockIdx.x & 15;
    const int u    = tid >> 5;           // warp = hidden unit within CTA
    const int lane = tid & 31;
    const int gate = lane >> 3;          // 0..3 (i,f,g,o)
    const int kc   = lane & 7;           // 0..7 k-chunk
    const int grow = gate * 256 + c * 16 + u;        // global gate row

    const float* whh = (l == 0) ? whh0 : (l == 1) ? whh1 : whh2;
    const float* wih = (l == 0) ? wih0 : (l == 1) ? wih1 : wih2;
    const float* bih = (l == 0) ? bih0 : (l == 1) ? bih1 : bih2;
    const float* bhh = (l == 0) ? bhh0 : (l == 1) ? bhh1 : bhh2;

    // W_hh slice: quad q covers floats [32q+4kc, 32q+4kc+4) -> conflict-free LDS.128
    unsigned long long wh[16];
    #pragma unroll
    for (int q = 0; q < 8; q++) {
        const float* pr = whh + grow * HID + 32 * q + 4 * kc;
        wh[2*q]   = *(const unsigned long long*)(pr);
        wh[2*q+1] = *(const unsigned long long*)(pr + 2);
    }
    unsigned long long wi[16];
    float wx[5];
    if (l == 0) {
        #pragma unroll
        for (int j = 0; j < 5; j++) wx[j] = wih[grow * F_IN + kc * 5 + j];
    } else {
        #pragma unroll
        for (int q = 0; q < 8; q++) {
            const float* pr = wih + grow * HID + 32 * q + 4 * kc;
            wi[2*q]   = *(const unsigned long long*)(pr);
            wi[2*q+1] = *(const unsigned long long*)(pr + 2);
        }
    }
    const float brow = bih[grow] + bhh[grow];

    // zero read-buffer 0 of h_s
    if (tid < 64) *(float4*)&h_s[0][tid * 4] = make_float4(0.f, 0.f, 0.f, 0.f);

    float xr = 0.0f;
    if (l == 0 && tid >= 256 && tid < 256 + F_IN)
        xr = x[(63 * T_STEPS + 0) * F_IN + (tid - 256)];

    float cst = 0.0f;                    // cell state (lane 0 of each warp)
    __syncthreads();

    for (int t = 0; t < T_STEPS; t++) {
        const int b = t & 1;

        // ---- stage inputs into parity buffer b ----
        if (tid < 256) {
            if (t > 0) h_s[b][tid] = poll_h(&g_hx[l][t-1][tid], t);
        } else if (l > 0) {
            hp_s[b][tid - 256] = poll_h(&g_hx[l-1][t][tid - 256], t + 1);
        } else {
            const int j = tid - 256;
            if (j < F_IN) {
                x_s[b][j] = xr;
                if (t + 1 < T_STEPS)
                    xr = x[(63 * T_STEPS + (t + 1)) * F_IN + j];
            }
        }
        __syncthreads();                 // the ONLY barrier per step

        // ---- matvec: 32-wide k-slice, packed f32x2, 2-way acc split ----
        unsigned long long a0 = 0ULL, a1 = 0ULL;
        {
            const float* hb = &h_s[b][4 * kc];
            #pragma unroll
            for (int q = 0; q < 8; q++) {
                float4 hv = *(const float4*)(hb + 32 * q);
                ffma2(a0, wh[2*q],   pack2(hv.x, hv.y));
                ffma2(a1, wh[2*q+1], pack2(hv.z, hv.w));
            }
        }
        float px = 0.0f;
        if (l > 0) {
            const float* pb = &hp_s[b][4 * kc];
            #pragma unroll
            for (int q = 0; q < 8; q++) {
                float4 hv = *(const float4*)(pb + 32 * q);
                ffma2(a0, wi[2*q],   pack2(hv.x, hv.y));
                ffma2(a1, wi[2*q+1], pack2(hv.z, hv.w));
            }
        } else {
            #pragma unroll
            for (int j = 0; j < 5; j++) px = fmaf(wx[j], x_s[b][kc * 5 + j], px);
        }
        float l0, h0, l1, h1;
        asm("mov.b64 {%0,%1}, %2;" : "=f"(l0), "=f"(h0) : "l"(a0));
        asm("mov.b64 {%0,%1}, %2;" : "=f"(l1), "=f"(h1) : "l"(a1));
        float p = (l0 + h0) + (l1 + h1) + px;

        // kc-reduce within each 8-lane gate group
        p += __shfl_xor_sync(0xffffffffu, p, 1);
        p += __shfl_xor_sync(0xffffffffu, p, 2);
        p += __shfl_xor_sync(0xffffffffu, p, 4);
        if (kc == 0) p += brow;

        // gather the 4 gate sums to lane 0; full gate math per-warp in parallel
        float gf = __shfl_sync(0xffffffffu, p, 8);
        float gg = __shfl_sync(0xffffffffu, p, 16);
        float go = __shfl_sync(0xffffffffu, p, 24);
        if (lane == 0) {
            float ii = sigf(p),  ff = sigf(gf);
            float cc = tanh_fast(gg), oo = sigf(go);
            cst = ff * cst + ii * cc;
            float hn = oo * tanh_fast(cst);
            pub_h(&g_hx[l][t][c * 16 + u], hn, t + 1);
        }
    }
}

// ---------------- classifier: logits = h2 @ W_lin^T + b, log_softmax ----------------
__global__ __launch_bounds__(512, 1) void classifier_kernel(
    const float* __restrict__ wlin,
    const float* __restrict__ blin,
    float* __restrict__ out)
{
    __shared__ float lg[4 * NSPK];
    __shared__ float hsm[4 * HID];
    __shared__ float rbuf[16];

    const int b    = blockIdx.x;
    const int t0   = b * 4;
    const int tid  = threadIdx.x;
    const int lane = tid & 31;
    const int wd   = tid >> 5;

    for (int i = tid; i < 4 * HID; i += 512)
        hsm[i] = g_hx[2][t0 + (i >> 8)][i & 255].x;
    __syncthreads();

    float hr[4][8];
    #pragma unroll
    for (int t = 0; t < 4; t++)
        #pragma unroll
        for (int j = 0; j < 8; j++) hr[t][j] = hsm[t * HID + lane * 8 + j];

    for (int o = wd; o < NSPK; o += 16) {
        const float4* wp = (const float4*)(wlin + o * HID + lane * 8);
        float4 w0 = wp[0], w1 = wp[1];
        float wv[8] = {w0.x, w0.y, w0.z, w0.w, w1.x, w1.y, w1.z, w1.w};
        float a0 = 0.f, a1 = 0.f, a2 = 0.f, a3 = 0.f;
        #pragma unroll
        for (int j = 0; j < 8; j++) {
            float wj = wv[j];
            a0 = fmaf(wj, hr[0][j], a0);
            a1 = fmaf(wj, hr[1][j], a1);
            a2 = fmaf(wj, hr[2][j], a2);
            a3 = fmaf(wj, hr[3][j], a3);
        }
        #pragma unroll
        for (int off = 16; off > 0; off >>= 1) {
            a0 += __shfl_xor_sync(0xffffffffu, a0, off);
            a1 += __shfl_xor_sync(0xffffffffu, a1, off);
            a2 += __shfl_xor_sync(0xffffffffu, a2, off);
            a3 += __shfl_xor_sync(0xffffffffu, a3, off);
        }
        if (lane == 0) {
            float bb = blin[o];
            lg[0 * NSPK + o] = a0 + bb;
            lg[1 * NSPK + o] = a1 + bb;
            lg[2 * NSPK + o] = a2 + bb;
            lg[3 * NSPK + o] = a3 + bb;
        }
    }
    __syncthreads();

    for (int t = 0; t < 4; t++) {
        float m = -1e30f;
        for (int o = tid; o < NSPK; o += 512) m = fmaxf(m, lg[t * NSPK + o]);
        #pragma unroll
        for (int off = 16; off > 0; off >>= 1)
            m = fmaxf(m, __shfl_xor_sync(0xffffffffu, m, off));
        if (lane == 0) rbuf[wd] = m;
        __syncthreads();
        float mm = rbuf[0];
        #pragma unroll
        for (int i = 1; i < 16; i++) mm = fmaxf(mm, rbuf[i]);
        __syncthreads();

        float s = 0.0f;
        for (int o = tid; o < NSPK; o += 512) s += __expf(lg[t * NSPK + o] - mm);
        #pragma unroll
        for (int off = 16; off > 0; off >>= 1)
            s += __shfl_xor_sync(0xffffffffu, s, off);
        if (lane == 0) rbuf[wd] = s;
        __syncthreads();
        float ss = 0.0f;
        #pragma unroll
        for (int i = 0; i < 16; i++) ss += rbuf[i];
        float lse = mm + logf(ss);

        for (int o = tid; o < NSPK; o += 512)
            out[(size_t)(t0 + t) * NSPK + o] = lg[t * NSPK + o] - lse;
        __syncthreads();
    }
}

// ---------------- launch ----------------
// Order: [lstm, classifier, reinit]. g_hx is zero at module load; reinit
// restores it to zero at the end of every call (same state for next call).
// Side effect: the ncu-captured launch (offset 0 mod 3) is now the LSTM kernel.
extern "C" void kernel_launch(void* const* d_in, const int* in_sizes, int n_in,
                              void* d_out, int out_size)
{
    const float* x    = (const float*)d_in[0];
    const float* wih0 = (const float*)d_in[1];
    const float* whh0 = (const float*)d_in[2];
    const float* bih0 = (const float*)d_in[3];
    const float* bhh0 = (const float*)d_in[4];
    const float* wih1 = (const float*)d_in[5];
    const float* whh1 = (const float*)d_in[6];
    const float* bih1 = (const float*)d_in[7];
    const float* bhh1 = (const float*)d_in[8];
    const float* wih2 = (const float*)d_in[9];
    const float* whh2 = (const float*)d_in[10];
    const float* bih2 = (const float*)d_in[11];
    const float* bhh2 = (const float*)d_in[12];
    const float* wlin = (const float*)d_in[13];
    const float* blin = (const float*)d_in[14];
    float* out = (float*)d_out;

    lstm_pipeline_kernel<<<48, 512>>>(x,
        wih0, whh0, bih0, bhh0,
        wih1, whh1, bih1, bhh1,
        wih2, whh2, bih2, bhh2);
    classifier_kernel<<<256, 512>>>(wlin, blin, out);
    reinit_epochs_kernel<<<1536, 512>>>();
}